// round 9
// baseline (speedup 1.0000x reference)
#include <cuda_runtime.h>
#include <cstdint>
#include <cstddef>

#define Ss 2048
#define Dd 512
#define Hh 8
#define DKk 64
#define BH 16
#define MM 4096
#define SCALE 0.125f

#define LDW 40                 // words per 32-k chunk row (32 data + 8 pad)
#define SLAB_A (128 * LDW)     // 5120 words
#define SLAB_B (64 * LDW)      // 2560 words

// ---------------- scratch ----------------
__device__ float g_Q[BH * Ss * DKk];     // [b,h,s,dk]
__device__ float g_K[BH * Ss * DKk];     // [b,h,s,dk]
__device__ float g_Vt[BH * DKk * Ss];    // [b,h,dk,s]
__device__ float g_O[MM * Dd];           // merged heads [b,s,d]

// ---------------- helpers ----------------
__device__ __forceinline__ uint32_t f2tf(float x) {
    uint32_t r;
    asm("cvt.rna.tf32.f32 %0, %1;" : "=r"(r) : "f"(x));
    return r;
}
__device__ __forceinline__ void mma_tf32(float& c0, float& c1, float& c2, float& c3,
                                         uint32_t a0, uint32_t a1, uint32_t a2, uint32_t a3,
                                         uint32_t b0, uint32_t b1) {
    asm volatile(
        "mma.sync.aligned.m16n8k8.row.col.f32.tf32.tf32.f32 "
        "{%0,%1,%2,%3}, {%4,%5,%6,%7}, {%8,%9}, {%0,%1,%2,%3};"
        : "+f"(c0), "+f"(c1), "+f"(c2), "+f"(c3)
        : "r"(a0), "r"(a1), "r"(a2), "r"(a3), "r"(b0), "r"(b1));
}

// Interleaved k-pair store: element k of a 32-k chunk goes to word
//   (k>>3)*8 + ((k&3)*2 + ((k>>2)&1) + 2*(row&3)) & 7
// so that step s, lane tk reads the pair (k=s*8+tk, k=s*8+tk+4) as one uint2.
__device__ __forceinline__ void st_ilv(uint32_t* rowp, int c4, int rot2, float4 v) {
    int grp = (c4 >> 1) * 8, beta = c4 & 1;
    rowp[grp + ((0 + beta + rot2) & 7)] = f2tf(v.x);
    rowp[grp + ((2 + beta + rot2) & 7)] = f2tf(v.y);
    rowp[grp + ((4 + beta + rot2) & 7)] = f2tf(v.z);
    rowp[grp + ((6 + beta + rot2) & 7)] = f2tf(v.w);
}

// One 32-k chunk of MMAs (4 k8 steps), conflict-free LDS.64 fragments.
__device__ __forceinline__ void mma_chunk32(const uint32_t* __restrict__ As,
                                            const uint32_t* __restrict__ Bs,
                                            float acc[2][4][4],
                                            int warp_m, int warp_n, int g, int tk) {
    const int rot2 = (g & 3) * 2;
    const int inner = (2 * tk + rot2) & 7;
#pragma unroll
    for (int s = 0; s < 4; s++) {
        uint2 a02[2], a13[2];
#pragma unroll
        for (int t = 0; t < 2; t++) {
            const uint32_t* p = As + (warp_m * 32 + t * 16 + g) * LDW + s * 8 + inner;
            a02[t] = *(const uint2*)p;
            a13[t] = *(const uint2*)(p + 8 * LDW);
        }
        uint2 bb[4];
#pragma unroll
        for (int u = 0; u < 4; u++) {
            const uint32_t* p = Bs + (warp_n * 32 + u * 8 + g) * LDW + s * 8 + inner;
            bb[u] = *(const uint2*)p;
        }
#pragma unroll
        for (int t = 0; t < 2; t++)
#pragma unroll
            for (int u = 0; u < 4; u++) {
                float* cc = acc[t][u];
                mma_tf32(cc[0], cc[1], cc[2], cc[3],
                         a02[t].x, a13[t].x, a02[t].y, a13[t].y,
                         bb[u].x, bb[u].y);
            }
    }
}

// =====================================================================
// Projection GEMM: C[m,n] = sum_k A[m,k] * B[n,k], K=512.
// MODE 0: -> head-split f32; MODE 1: -> Vt f32; MODE 2: -> plain f32 [m,Dd]
// =====================================================================
template <int MODE>
__global__ __launch_bounds__(256, 2) void gemm_k(
    const float* __restrict__ A, const float* __restrict__ B,
    float* __restrict__ Out)
{
    const int m0 = blockIdx.y * 128;
    const int n0 = blockIdx.x * 64;
    const int tid = threadIdx.x;
    const int lane = tid & 31, wid = tid >> 5;
    const int warp_m = wid & 3, warp_n = wid >> 2;
    const int g = lane >> 2, tk = lane & 3;

    __shared__ uint32_t As[SLAB_A];
    __shared__ uint32_t Bs[SLAB_B];

    float acc[2][4][4];
#pragma unroll
    for (int t = 0; t < 2; t++)
#pragma unroll
        for (int u = 0; u < 4; u++)
#pragma unroll
            for (int j = 0; j < 4; j++) acc[t][u][j] = 0.f;

    float4 pa[4], pb[2];
#pragma unroll
    for (int i = 0; i < 4; i++) {
        int v = tid + 256 * i, row = v >> 3, c4 = v & 7;
        pa[i] = *(const float4*)&A[(size_t)(m0 + row) * Dd + c4 * 4];
    }
#pragma unroll
    for (int i = 0; i < 2; i++) {
        int v = tid + 256 * i, row = v >> 3, c4 = v & 7;
        pb[i] = *(const float4*)&B[(size_t)(n0 + row) * Dd + c4 * 4];
    }

    for (int c = 0; c < 16; c++) {
#pragma unroll
        for (int i = 0; i < 4; i++) {
            int v = tid + 256 * i, row = v >> 3, c4 = v & 7;
            st_ilv(&As[row * LDW], c4, (row & 3) * 2, pa[i]);
        }
#pragma unroll
        for (int i = 0; i < 2; i++) {
            int v = tid + 256 * i, row = v >> 3, c4 = v & 7;
            st_ilv(&Bs[row * LDW], c4, (row & 3) * 2, pb[i]);
        }
        __syncthreads();
        if (c + 1 < 16) {
            const int k1 = (c + 1) * 32;
#pragma unroll
            for (int i = 0; i < 4; i++) {
                int v = tid + 256 * i, row = v >> 3, c4 = v & 7;
                pa[i] = *(const float4*)&A[(size_t)(m0 + row) * Dd + k1 + c4 * 4];
            }
#pragma unroll
            for (int i = 0; i < 2; i++) {
                int v = tid + 256 * i, row = v >> 3, c4 = v & 7;
                pb[i] = *(const float4*)&B[(size_t)(n0 + row) * Dd + k1 + c4 * 4];
            }
        }
        mma_chunk32(As, Bs, acc, warp_m, warp_n, g, tk);
        __syncthreads();
    }

#pragma unroll
    for (int t = 0; t < 2; t++) {
#pragma unroll
        for (int half = 0; half < 2; half++) {
            const int m = m0 + warp_m * 32 + t * 16 + g + half * 8;
#pragma unroll
            for (int u = 0; u < 4; u++) {
                const int n = n0 + warp_n * 32 + u * 8 + tk * 2;
                float v0 = acc[t][u][half * 2 + 0];
                float v1 = acc[t][u][half * 2 + 1];
                if (MODE == 0) {
                    int b = m >> 11, s = m & 2047;
                    int h = n >> 6, dk = n & 63;
                    *(float2*)&Out[(((size_t)(b * Hh + h) * Ss + s) * DKk) + dk] =
                        make_float2(v0, v1);
                } else if (MODE == 1) {
                    int b = m >> 11, s = m & 2047;
                    int h = n >> 6, dk = n & 63;
                    size_t i0 = ((size_t)(b * Hh + h) * DKk + dk) * Ss + s;
                    Out[i0] = v0;
                    Out[i0 + Ss] = v1;
                } else {
                    *(float2*)&Out[(size_t)m * Dd + n] = make_float2(v0, v1);
                }
            }
        }
    }
}

// =====================================================================
// Fused attention: per (bh, 128-row m-tile).
// Pass 1: S = Q K^T, rowsum of exp(S/8).
// Pass 2: recompute S, P = exp(S/8)/l written to gmem, O += P V.
// =====================================================================
#define FUSED_SMEM_WORDS (2 * SLAB_A /*Q*/ + 2 * SLAB_A /*P*/ + 2 * SLAB_B /*KV*/ + 384)

__global__ __launch_bounds__(256, 2) void fused_attn(
    const float* __restrict__ Q, const float* __restrict__ Kt,
    const float* __restrict__ Vt, float* __restrict__ P, float* __restrict__ O)
{
    const int bh = blockIdx.y;
    const int b_ = bh >> 3, h_ = bh & 7;
    const int m0 = blockIdx.x * 128;
    const float* Qb = Q + (size_t)bh * Ss * DKk;
    const float* Kb = Kt + (size_t)bh * Ss * DKk;
    const float* Vb = Vt + (size_t)bh * DKk * Ss;
    float* Pb = P + (size_t)bh * Ss * Ss;

    extern __shared__ uint32_t sm[];
    uint32_t* Qbuf = sm;                        // 2 slabs (dk chunks)
    uint32_t* Pbuf = sm + 2 * SLAB_A;           // 2 slabs (j chunks)
    uint32_t* Bbuf = sm + 4 * SLAB_A;           // 2 slabs (K or V chunk)
    float* rs2 = (float*)(sm + 4 * SLAB_A + 2 * SLAB_B);   // [2][128]
    float* sinv = rs2 + 256;                    // [128]

    const int tid = threadIdx.x;
    const int lane = tid & 31, wid = tid >> 5;
    const int warp_m = wid & 3, warp_n = wid >> 2;
    const int g = lane >> 2, tk = lane & 3;

    // ---- load Q tile once (both dk chunks) ----
#pragma unroll
    for (int c = 0; c < 2; c++)
#pragma unroll
        for (int i = 0; i < 4; i++) {
            int v = tid + 256 * i, row = v >> 3, c4 = v & 7;
            float4 q = *(const float4*)&Qb[(size_t)(m0 + row) * DKk + c * 32 + c4 * 4];
            st_ilv(&Qbuf[c * SLAB_A + row * LDW], c4, (row & 3) * 2, q);
        }

    float rsum[2][2] = {{0.f, 0.f}, {0.f, 0.f}};
    float oacc[2][4][4];
#pragma unroll
    for (int t = 0; t < 2; t++)
#pragma unroll
        for (int u = 0; u < 4; u++)
#pragma unroll
            for (int j = 0; j < 4; j++) oacc[t][u][j] = 0.f;

    // K prefetch registers (2 slabs x 2 float4)
    float4 pk[4];
#pragma unroll
    for (int c = 0; c < 2; c++)
#pragma unroll
        for (int i = 0; i < 2; i++) {
            int v = tid + 256 * i, row = v >> 3, c4 = v & 7;
            pk[c * 2 + i] = *(const float4*)&Kb[(size_t)row * DKk + c * 32 + c4 * 4];
        }
    __syncthreads();   // Qbuf ready

    // ================= PASS 1 =================
    for (int n0 = 0; n0 < Ss; n0 += 64) {
#pragma unroll
        for (int c = 0; c < 2; c++)
#pragma unroll
            for (int i = 0; i < 2; i++) {
                int v = tid + 256 * i, row = v >> 3, c4 = v & 7;
                st_ilv(&Bbuf[c * SLAB_B + row * LDW], c4, (row & 3) * 2, pk[c * 2 + i]);
            }
        __syncthreads();

        if (n0 + 64 < Ss) {
#pragma unroll
            for (int c = 0; c < 2; c++)
#pragma unroll
                for (int i = 0; i < 2; i++) {
                    int v = tid + 256 * i, row = v >> 3, c4 = v & 7;
                    pk[c * 2 + i] = *(const float4*)
                        &Kb[(size_t)(n0 + 64 + row) * DKk + c * 32 + c4 * 4];
                }
        }

        float sacc[2][4][4];
#pragma unroll
        for (int t = 0; t < 2; t++)
#pragma unroll
            for (int u = 0; u < 4; u++)
#pragma unroll
                for (int j = 0; j < 4; j++) sacc[t][u][j] = 0.f;
        mma_chunk32(Qbuf, Bbuf, sacc, warp_m, warp_n, g, tk);
        mma_chunk32(Qbuf + SLAB_A, Bbuf + SLAB_B, sacc, warp_m, warp_n, g, tk);

#pragma unroll
        for (int t = 0; t < 2; t++)
#pragma unroll
            for (int half = 0; half < 2; half++) {
                float rp = 0.f;
#pragma unroll
                for (int u = 0; u < 4; u++) {
                    rp += __expf(sacc[t][u][half * 2 + 0] * SCALE);
                    rp += __expf(sacc[t][u][half * 2 + 1] * SCALE);
                }
                rsum[t][half] += rp;
            }
        __syncthreads();
    }

    // ---- rowsum reduce -> sinv ----
#pragma unroll
    for (int t = 0; t < 2; t++)
#pragma unroll
        for (int half = 0; half < 2; half++) {
            float r = rsum[t][half];
            r += __shfl_xor_sync(0xffffffffu, r, 1);
            r += __shfl_xor_sync(0xffffffffu, r, 2);
            if (tk == 0)
                rs2[warp_n * 128 + warp_m * 32 + t * 16 + half * 8 + g] = r;
        }
    __syncthreads();
    if (tid < 128) sinv[tid] = 1.f / (rs2[tid] + rs2[128 + tid]);
    __syncthreads();

    float inv[2][2];
#pragma unroll
    for (int t = 0; t < 2; t++)
#pragma unroll
        for (int half = 0; half < 2; half++)
            inv[t][half] = sinv[warp_m * 32 + t * 16 + half * 8 + g];

    // reload K prefetch for pass 2
#pragma unroll
    for (int c = 0; c < 2; c++)
#pragma unroll
        for (int i = 0; i < 2; i++) {
            int v = tid + 256 * i, row = v >> 3, c4 = v & 7;
            pk[c * 2 + i] = *(const float4*)&Kb[(size_t)row * DKk + c * 32 + c4 * 4];
        }

    // ================= PASS 2 =================
    for (int n0 = 0; n0 < Ss; n0 += 64) {
#pragma unroll
        for (int c = 0; c < 2; c++)
#pragma unroll
            for (int i = 0; i < 2; i++) {
                int v = tid + 256 * i, row = v >> 3, c4 = v & 7;
                st_ilv(&Bbuf[c * SLAB_B + row * LDW], c4, (row & 3) * 2, pk[c * 2 + i]);
            }
        __syncthreads();

        if (n0 + 64 < Ss) {
#pragma unroll
            for (int c = 0; c < 2; c++)
#pragma unroll
                for (int i = 0; i < 2; i++) {
                    int v = tid + 256 * i, row = v >> 3, c4 = v & 7;
                    pk[c * 2 + i] = *(const float4*)
                        &Kb[(size_t)(n0 + 64 + row) * DKk + c * 32 + c4 * 4];
                }
        }

        float sacc[2][4][4];
#pragma unroll
        for (int t = 0; t < 2; t++)
#pragma unroll
            for (int u = 0; u < 4; u++)
#pragma unroll
                for (int j = 0; j < 4; j++) sacc[t][u][j] = 0.f;
        mma_chunk32(Qbuf, Bbuf, sacc, warp_m, warp_n, g, tk);
        mma_chunk32(Qbuf + SLAB_A, Bbuf + SLAB_B, sacc, warp_m, warp_n, g, tk);

        // p = exp(s/8) * inv, write gmem
#pragma unroll
        for (int t = 0; t < 2; t++)
#pragma unroll
            for (int half = 0; half < 2; half++) {
                const int m = warp_m * 32 + t * 16 + half * 8 + g;
#pragma unroll
                for (int u = 0; u < 4; u++) {
                    float p0 = __expf(sacc[t][u][half * 2 + 0] * SCALE) * inv[t][half];
                    float p1 = __expf(sacc[t][u][half * 2 + 1] * SCALE) * inv[t][half];
                    sacc[t][u][half * 2 + 0] = p0;
                    sacc[t][u][half * 2 + 1] = p1;
                    const int n = warp_n * 32 + u * 8 + tk * 2;
                    *(float2*)&Pb[(size_t)(m0 + m) * Ss + n0 + n] = make_float2(p0, p1);
                }
            }
        __syncthreads();   // S-MMA done everywhere; Bbuf & Pbuf free

        // store p -> Pbuf (A layout, slab = warp_n)
#pragma unroll
        for (int t = 0; t < 2; t++)
#pragma unroll
            for (int half = 0; half < 2; half++) {
                const int r = warp_m * 32 + t * 16 + half * 8 + g;
                uint32_t* rowp = &Pbuf[warp_n * SLAB_A + r * LDW];
                const int rot2 = (g & 3) * 2;
#pragma unroll
                for (int u = 0; u < 4; u++) {
                    // col kk = u*8 + 2*tk  ->  grp=u, beta=tk>>1, j=2*(tk&1)
                    int inner = (4 * (tk & 1) + (tk >> 1) + rot2) & 7;
                    rowp[u * 8 + inner] = f2tf(sacc[t][u][half * 2 + 0]);
                    rowp[u * 8 + ((inner + 2) & 7)] = f2tf(sacc[t][u][half * 2 + 1]);
                }
            }
        // load V chunks -> Bbuf
#pragma unroll
        for (int c = 0; c < 2; c++)
#pragma unroll
            for (int i = 0; i < 2; i++) {
                int v = tid + 256 * i, row = v >> 3, c4 = v & 7;
                float4 vv = *(const float4*)&Vb[(size_t)row * Ss + n0 + c * 32 + c4 * 4];
                st_ilv(&Bbuf[c * SLAB_B + row * LDW], c4, (row & 3) * 2, vv);
            }
        __syncthreads();   // Pbuf + V ready

        mma_chunk32(Pbuf, Bbuf, oacc, warp_m, warp_n, g, tk);
        mma_chunk32(Pbuf + SLAB_A, Bbuf + SLAB_B, oacc, warp_m, warp_n, g, tk);
        __syncthreads();   // PV done; buffers free for next iter
    }

    // ---- O epilogue (already normalized) ----
#pragma unroll
    for (int t = 0; t < 2; t++)
#pragma unroll
        for (int half = 0; half < 2; half++) {
            const int m = m0 + warp_m * 32 + t * 16 + half * 8 + g;
#pragma unroll
            for (int u = 0; u < 4; u++) {
                const int n = warp_n * 32 + u * 8 + tk * 2;
                *(float2*)&O[((size_t)(b_ * Ss + m)) * Dd + h_ * DKk + n] =
                    make_float2(oacc[t][u][half * 2 + 0], oacc[t][u][half * 2 + 1]);
            }
        }
}

// ---------------- launch ----------------
extern "C" void kernel_launch(void* const* d_in, const int* in_sizes, int n_in,
                              void* d_out, int out_size)
{
    const float* query = (const float*)d_in[0];
    const float* key   = (const float*)d_in[1];
    const float* value = (const float*)d_in[2];
    const float* w_q   = (const float*)d_in[3];
    const float* w_k   = (const float*)d_in[4];
    const float* w_v   = (const float*)d_in[5];
    const float* w_o   = (const float*)d_in[6];

    float* out_main = (float*)d_out;
    float* p_attn   = out_main + (size_t)MM * Dd;

    float *Qp, *Kp, *Vp, *Op;
    cudaGetSymbolAddress((void**)&Qp, g_Q);
    cudaGetSymbolAddress((void**)&Kp, g_K);
    cudaGetSymbolAddress((void**)&Vp, g_Vt);
    cudaGetSymbolAddress((void**)&Op, g_O);

    const int fused_smem = FUSED_SMEM_WORDS * 4;
    cudaFuncSetAttribute(fused_attn, cudaFuncAttributeMaxDynamicSharedMemorySize,
                         fused_smem);

    dim3 pj_grid(Dd / 64, MM / 128);   // (8, 32)
    gemm_k<0><<<pj_grid, 256>>>(query, w_q, Qp);
    gemm_k<0><<<pj_grid, 256>>>(key,   w_k, Kp);
    gemm_k<1><<<pj_grid, 256>>>(value, w_v, Vp);

    dim3 fa_grid(Ss / 128, BH);        // (16, 16)
    fused_attn<<<fa_grid, 256, fused_smem>>>(Qp, Kp, Vp, p_attn, Op);

    gemm_k<2><<<pj_grid, 256>>>(Op, w_o, out_main);
}